// round 6
// baseline (speedup 1.0000x reference)
#include <cuda_runtime.h>
#include <cuda_bf16.h>
#include <cstdint>

#define NTOK_MAX (8 * 4096)
#define IN_F 1024
#define CUT1 5000
#define CUT2 20000

__device__ int g_cnt[2];
__device__ int g_idx0[NTOK_MAX];
__device__ int g_idx1[NTOK_MAX];

// ---------------------------------------------------------------------------
__global__ void init_k() { g_cnt[0] = 0; g_cnt[1] = 0; }

__global__ void classify_k(const int* __restrict__ tokens, int n) {
    int i = blockIdx.x * blockDim.x + threadIdx.x;
    int t = (i < n) ? tokens[i] : -1;
    int c = (t >= CUT2) ? 1 : ((t >= CUT1) ? 0 : -1);
    int lane = threadIdx.x & 31;
#pragma unroll
    for (int cc = 0; cc < 2; ++cc) {
        unsigned m = __ballot_sync(0xffffffffu, c == cc);
        if (c == cc) {
            int leader = __ffs(m) - 1;
            int base = 0;
            if (lane == leader) base = atomicAdd(&g_cnt[cc], __popc(m));
            base = __shfl_sync(m, base, leader);
            int off = base + __popc(m & ((1u << lane) - 1u));
            if (cc == 0) g_idx0[off] = i;
            else         g_idx1[off] = i;
        }
    }
}

__global__ void head_copy_k(const int* __restrict__ tokens,
                            const float* __restrict__ head_emb,
                            float* __restrict__ out) {
    int p = blockIdx.x;
    int t = __ldg(&tokens[p]);
    if (t >= CUT1) return;
    const float4* src = (const float4*)(head_emb + (size_t)t * IN_F);
    float4* dst = (float4*)(out + (size_t)p * IN_F);
    dst[threadIdx.x]       = src[threadIdx.x];
    dst[threadIdx.x + 128] = src[threadIdx.x + 128];
}

// ---------------------------------------------------------------------------
__device__ __forceinline__ void hilo2(float f0, float f1,
                                      uint32_t& hi2, uint32_t& lo2) {
    uint32_t h;
    asm("cvt.rn.bf16x2.f32 %0, %1, %2;" : "=r"(h) : "f"(f1), "f"(f0));
    float r0 = f0 - __uint_as_float(h << 16);          // exact
    float r1 = f1 - __uint_as_float(h & 0xffff0000u);  // exact
    asm("cvt.rn.bf16x2.f32 %0, %1, %2;" : "=r"(lo2) : "f"(r1), "f"(r0));
    hi2 = h;
}

__device__ __forceinline__ void ldsm_x4(uint32_t& r0, uint32_t& r1,
                                        uint32_t& r2, uint32_t& r3,
                                        const void* smem_ptr) {
    uint32_t addr = (uint32_t)__cvta_generic_to_shared(smem_ptr);
    asm volatile("ldmatrix.sync.aligned.m8n8.x4.shared.b16 {%0,%1,%2,%3}, [%4];"
                 : "=r"(r0), "=r"(r1), "=r"(r2), "=r"(r3) : "r"(addr));
}

__device__ __forceinline__ void mma16816(float* c, const uint32_t* a,
                                         uint32_t b0, uint32_t b1) {
    asm volatile(
        "mma.sync.aligned.m16n8k16.row.col.f32.bf16.bf16.f32 "
        "{%0,%1,%2,%3}, {%4,%5,%6,%7}, {%8,%9}, {%0,%1,%2,%3};"
        : "+f"(c[0]), "+f"(c[1]), "+f"(c[2]), "+f"(c[3])
        : "r"(a[0]), "r"(a[1]), "r"(a[2]), "r"(a[3]), "r"(b0), "r"(b1));
}

// ---------------------------------------------------------------------------
// Fused gather + split-bf16 tensor GEMM. Tile 128(M) x 128(N), TK=32 floats.
// Per chunk: convert once to Ah/Al/Bh/Bl smem, 3 split products per output:
//   AhBh + AlBh + AhBl.  Warp tile 64x32 (2M x 4N warps).
template <int K, int LOW, int C>
__global__ void __launch_bounds__(256, 1)
tail_fused_k(const float* __restrict__ emb,
             const float* __restrict__ w,
             const int* __restrict__ tokens,
             float* __restrict__ out) {
    constexpr int TM = 128, TN = 128, LD = 40;   // LD halves: 32 + 8 pad
    constexpr int NC = K / 32;
    __shared__ __align__(16) __nv_bfloat16 sAh[TM][LD];
    __shared__ __align__(16) __nv_bfloat16 sAl[TM][LD];
    __shared__ __align__(16) __nv_bfloat16 sBh[TN][LD];
    __shared__ __align__(16) __nv_bfloat16 sBl[TN][LD];
    __shared__ int sPos[TM];

    const int count = g_cnt[C];
    const int rowBase = blockIdx.x * TM;
    if (rowBase >= count) return;
    const int rem = min(TM, count - rowBase);
    const int n0 = blockIdx.y * TN;
    const int tid = threadIdx.x;
    const int lane = tid & 31;
    const int wid = tid >> 5;
    const int* idxList = (C == 0) ? g_idx0 : g_idx1;

    if (tid < TM) sPos[tid] = idxList[rowBase + min(tid, rem - 1)];
    __syncthreads();

    // loaders: 2 threads per row, 16 floats each (A: 128 rows, B: 128 rows)
    const int ar = tid >> 1;
    const int aseg = (tid & 1) * 16;
    const float* aPtr = emb + (size_t)(__ldg(&tokens[sPos[ar]]) - LOW) * K + aseg;
    const float* bPtr = w + (size_t)(n0 + ar) * K + aseg;

    float ra[16], rb[16];
#define PREFETCH(kc)                                              \
    do {                                                          \
        const float* ap_ = aPtr + (kc) * 32;                      \
        const float* bp_ = bPtr + (kc) * 32;                      \
        _Pragma("unroll")                                         \
        for (int q_ = 0; q_ < 4; q_++) {                          \
            float4 va_ = *(const float4*)(ap_ + q_ * 4);          \
            float4 vb_ = *(const float4*)(bp_ + q_ * 4);          \
            ra[q_*4+0]=va_.x; ra[q_*4+1]=va_.y;                   \
            ra[q_*4+2]=va_.z; ra[q_*4+3]=va_.w;                   \
            rb[q_*4+0]=vb_.x; rb[q_*4+1]=vb_.y;                   \
            rb[q_*4+2]=vb_.z; rb[q_*4+3]=vb_.w;                   \
        }                                                         \
    } while (0)

    PREFETCH(0);

    const int wm = (wid & 1) * 64;
    const int wn = (wid >> 1) * 32;
    float c[4][4][4];
#pragma unroll
    for (int i = 0; i < 4; i++)
#pragma unroll
        for (int j = 0; j < 4; j++)
#pragma unroll
            for (int q = 0; q < 4; q++) c[i][j][q] = 0.f;

    const int aLdRow = lane & 15;
    const int aLdCol = (lane >> 4) * 8;
    const int bLdRow = ((lane >> 4) << 3) + (lane & 7);
    const int bLdCol = lane & 8;

    for (int kc = 0; kc < NC; kc++) {
        __syncthreads();  // previous MMA done reading smem
        // convert + store chunk kc
#pragma unroll
        for (int q = 0; q < 2; q++) {
            uint32_t h0, h1, h2, h3, l0, l1, l2, l3;
            hilo2(ra[q*8+0], ra[q*8+1], h0, l0);
            hilo2(ra[q*8+2], ra[q*8+3], h1, l1);
            hilo2(ra[q*8+4], ra[q*8+5], h2, l2);
            hilo2(ra[q*8+6], ra[q*8+7], h3, l3);
            *(uint4*)&sAh[ar][aseg + q*8] = make_uint4(h0, h1, h2, h3);
            *(uint4*)&sAl[ar][aseg + q*8] = make_uint4(l0, l1, l2, l3);
            hilo2(rb[q*8+0], rb[q*8+1], h0, l0);
            hilo2(rb[q*8+2], rb[q*8+3], h1, l1);
            hilo2(rb[q*8+4], rb[q*8+5], h2, l2);
            hilo2(rb[q*8+6], rb[q*8+7], h3, l3);
            *(uint4*)&sBh[ar][aseg + q*8] = make_uint4(h0, h1, h2, h3);
            *(uint4*)&sBl[ar][aseg + q*8] = make_uint4(l0, l1, l2, l3);
        }
        __syncthreads();

        if (kc + 1 < NC) PREFETCH(kc + 1);  // latency hides under MMA

#pragma unroll
        for (int kf = 0; kf < 2; kf++) {
            uint32_t AhF[4][4], AlF[4][4], BhF[2][4], BlF[2][4];
#pragma unroll
            for (int mf = 0; mf < 4; mf++) {
                ldsm_x4(AhF[mf][0], AhF[mf][1], AhF[mf][2], AhF[mf][3],
                        &sAh[wm + mf * 16 + aLdRow][kf * 16 + aLdCol]);
                ldsm_x4(AlF[mf][0], AlF[mf][1], AlF[mf][2], AlF[mf][3],
                        &sAl[wm + mf * 16 + aLdRow][kf * 16 + aLdCol]);
            }
#pragma unroll
            for (int g = 0; g < 2; g++) {
                ldsm_x4(BhF[g][0], BhF[g][1], BhF[g][2], BhF[g][3],
                        &sBh[wn + g * 16 + bLdRow][kf * 16 + bLdCol]);
                ldsm_x4(BlF[g][0], BlF[g][1], BlF[g][2], BlF[g][3],
                        &sBl[wn + g * 16 + bLdRow][kf * 16 + bLdCol]);
            }
#pragma unroll
            for (int mf = 0; mf < 4; mf++)
#pragma unroll
                for (int nf = 0; nf < 4; nf++) {
                    uint32_t bh0 = BhF[nf >> 1][(nf & 1) * 2];
                    uint32_t bh1 = BhF[nf >> 1][(nf & 1) * 2 + 1];
                    mma16816(c[mf][nf], AhF[mf], bh0, bh1);
                    mma16816(c[mf][nf], AlF[mf], bh0, bh1);
                    mma16816(c[mf][nf], AhF[mf],
                             BlF[nf >> 1][(nf & 1) * 2],
                             BlF[nf >> 1][(nf & 1) * 2 + 1]);
                }
        }
    }
#undef PREFETCH

    // scatter epilogue
#pragma unroll
    for (int mf = 0; mf < 4; mf++) {
#pragma unroll
        for (int nf = 0; nf < 4; nf++) {
            int r0 = wm + mf * 16 + (lane >> 2);
            int col = n0 + wn + nf * 8 + 2 * (lane & 3);
            if (r0 < rem)
                *(float2*)(out + (size_t)sPos[r0] * IN_F + col) =
                    make_float2(c[mf][nf][0], c[mf][nf][1]);
            if (r0 + 8 < rem)
                *(float2*)(out + (size_t)sPos[r0 + 8] * IN_F + col) =
                    make_float2(c[mf][nf][2], c[mf][nf][3]);
        }
    }
}

// ---------------------------------------------------------------------------
extern "C" void kernel_launch(void* const* d_in, const int* in_sizes, int n_in,
                              void* d_out, int out_size) {
    const int*   tokens   = (const int*)d_in[0];
    const float* head_emb = (const float*)d_in[1];
    const float* t0e      = (const float*)d_in[2];
    const float* t0w      = (const float*)d_in[3];
    const float* t1e      = (const float*)d_in[4];
    const float* t1w      = (const float*)d_in[5];
    float* out = (float*)d_out;
    int n = in_sizes[0];
    if (n > NTOK_MAX) n = NTOK_MAX;

    init_k<<<1, 1>>>();
    classify_k<<<(n + 255) / 256, 256>>>(tokens, n);
    head_copy_k<<<n, 128>>>(tokens, head_emb, out);

    dim3 grid((n + 127) / 128, IN_F / 128);
    tail_fused_k<512, CUT1, 0><<<grid, 256>>>(t0e, t0w, tokens, out);
    tail_fused_k<256, CUT2, 1><<<grid, 256>>>(t1e, t1w, tokens, out);
}